// round 6
// baseline (speedup 1.0000x reference)
#include <cuda_runtime.h>
#include <cstdint>
#include <cstddef>

#define NB 512
#define NN 1000
#define TILE 64
#define SP 132                       // padded floats per tile row (128+4)
#define TILE_FLOATS (TILE * SP)      // 8448
#define TILE_BYTES (TILE_FLOATS * 4) // 33792

using u64 = unsigned long long;

__device__ __forceinline__ u64 pack2(float lo, float hi) {
    u64 r; asm("mov.b64 %0, {%1, %2};" : "=l"(r) : "f"(lo), "f"(hi)); return r;
}
__device__ __forceinline__ void unpack2(u64 v, float& lo, float& hi) {
    asm("mov.b64 {%0, %1}, %2;" : "=f"(lo), "=f"(hi) : "l"(v));
}
__device__ __forceinline__ u64 ffma2(u64 a, u64 b, u64 c) {
    u64 d; asm("fma.rn.f32x2 %0, %1, %2, %3;" : "=l"(d) : "l"(a), "l"(b), "l"(c)); return d;
}
__device__ __forceinline__ void cp16(uint32_t s, const void* g) {
    asm volatile("cp.async.cg.shared.global [%0], [%1], 16;" :: "r"(s), "l"(g));
}
__device__ __forceinline__ void cp_commit() { asm volatile("cp.async.commit_group;"); }
__device__ __forceinline__ void cp_wait1() { asm volatile("cp.async.wait_group 1;"); }
__device__ __forceinline__ void cp_wait0() { asm volatile("cp.async.wait_group 0;"); }

__global__ __launch_bounds__(256, 2)
void fused_ptr_attn_kernel(const float* __restrict__ state,   // [B,384]
                           const float* __restrict__ ctx,     // [B,N,128]
                           const int*   __restrict__ mask,    // [B,N]
                           const float* __restrict__ Wq,      // [384,128]
                           const float* __restrict__ Wkm,     // [128,128]
                           const float* __restrict__ Wv,      // [128,128]
                           const float* __restrict__ Wfc,     // [128,128]
                           const float* __restrict__ Wk,      // [128,128]
                           const int*   __restrict__ Tp,
                           float* __restrict__ out)           // [B,N]
{
    extern __shared__ __align__(16) float dynbuf[];  // 2 * TILE_FLOATS

    __shared__ __align__(16) float s_state[384];
    __shared__ __align__(16) float s_q[128];
    __shared__ __align__(16) float s_Qt[8][SP];    // padded rows: conflict-free head reads
    __shared__ __align__(16) float s_e[TILE][8];
    __shared__ __align__(16) float s_sunf[8][128];
    __shared__ __align__(16) float s_x128[2][128];
    __shared__ __align__(16) float s_xfc[2][128];
    __shared__ __align__(16) float s_y[128];
    __shared__ __align__(16) float s_p[NN];
    __shared__ short s_idx[NN];
    __shared__ int   s_cnt;
    __shared__ float s_den[8][8];
    __shared__ float s_denf[8];
    __shared__ float s_den2[8];
    __shared__ float s_inv;

    const int t    = threadIdx.x;
    const int w    = t >> 5;
    const int lane = t & 31;
    const int b    = blockIdx.x;
    const float4* ctx4 = reinterpret_cast<const float4*>(ctx + (size_t)b * NN * 128);
    const uint32_t dyn_s = (uint32_t)__cvta_generic_to_shared(dynbuf);

    // ---------------- prologue ----------------
    if (t < 128) {
        s_state[t]       = state[(size_t)b * 384 + t];
        s_state[t + 128] = state[(size_t)b * 384 + 128 + t];
        s_state[t + 256] = state[(size_t)b * 384 + 256 + t];
    }
    for (int i = t; i < NN; i += 256) s_p[i] = 0.f;
    __syncthreads();

    // warp 0: compact unmasked indices; threads 128..255: q = state @ Wq
    if (w == 0) {
        int base = 0;
        const int* mb = mask + (size_t)b * NN;
        for (int i0 = 0; i0 < NN; i0 += 32) {
            int n = i0 + lane;
            int m = (n < NN) ? __ldg(&mb[n]) : 1;
            unsigned bal = __ballot_sync(0xffffffffu, m == 0);
            if (m == 0) {
                int pre = __popc(bal & ((1u << lane) - 1u));
                s_idx[base + pre] = (short)n;
            }
            base += __popc(bal);
        }
        if (lane == 0) s_cnt = base;
    } else if (t >= 128) {
        int col = t - 128;
        float a0 = 0.f, a1 = 0.f, a2 = 0.f, a3 = 0.f;
        #pragma unroll 4
        for (int i = 0; i < 384; i += 4) {
            a0 = fmaf(s_state[i    ], __ldg(&Wq[(i    ) * 128 + col]), a0);
            a1 = fmaf(s_state[i + 1], __ldg(&Wq[(i + 1) * 128 + col]), a1);
            a2 = fmaf(s_state[i + 2], __ldg(&Wq[(i + 2) * 128 + col]), a2);
            a3 = fmaf(s_state[i + 3], __ldg(&Wq[(i + 3) * 128 + col]), a3);
        }
        s_q[col] = (a0 + a1) + (a2 + a3);
    }
    __syncthreads();

    const int cnt    = s_cnt;
    const int ntiles = (cnt + TILE - 1) / TILE;

    // tile loader: one warp per 8 rows, one row per warp-iteration (coalesced 512B)
    auto load_tile = [&](int tile, int stage) {
        if ((unsigned)tile < (unsigned)ntiles) {
            uint32_t base = dyn_s + stage * TILE_BYTES;
            #pragma unroll
            for (int i = 0; i < 8; i++) {
                int j = tile * TILE + w * 8 + i;
                int n = (j < cnt) ? (int)s_idx[j] : (int)s_idx[0];
                cp16(base + ((w * 8 + i) * SP + lane * 4) * 4, ctx4 + n * 32 + lane);
            }
        }
        cp_commit();
    };

    // kick off tiles 0,1 before Qt compute (covers initial DRAM latency)
    load_tile(0, 0);
    load_tile(1, 1);

    // ---------------- Qt[h][d] = 0.25 * sum_j Wkm[d][16h+j] * q[16h+j] ----------------
    {
        const int hw    = w & 3;
        const int dbase = (w >> 2) * 64;
        const int hid   = hw * 32 + lane;
        const float ql  = s_q[hid];
        const int head0 = hw * 2 + (lane >> 4);
        #pragma unroll 4
        for (int dd = 0; dd < 64; dd++) {
            int d = dbase + dd;
            float p = __ldg(&Wkm[d * 128 + hid]) * ql;
            p += __shfl_xor_sync(0xffffffffu, p, 8);
            p += __shfl_xor_sync(0xffffffffu, p, 4);
            p += __shfl_xor_sync(0xffffffffu, p, 2);
            p += __shfl_xor_sync(0xffffffffu, p, 1);
            if ((lane & 15) == 0) s_Qt[head0][d] = 0.25f * p;
        }
    }
    __syncthreads();

    // ---------------- pass 1: tiles, shuffle-free ----------------
    u64 acc2[8][2];
    #pragma unroll
    for (int h = 0; h < 8; h++) { acc2[h][0] = 0ull; acc2[h][1] = 0ull; }
    float den_l = 0.f;

    const int r_b   = t >> 2;        // phase-B row
    const int sub   = t & 3;         // phase-B head pair
    const float4* q0 = reinterpret_cast<const float4*>(s_Qt[2 * sub]);
    const float4* q1 = reinterpret_cast<const float4*>(s_Qt[2 * sub + 1]);

    for (int i = 0; i < ntiles; i++) {
        cp_wait1();
        __syncthreads();
        const float* tb = dynbuf + (i & 1) * TILE_FLOATS;

        // phase B: dots + exp, one thread per (row, head-pair)
        {
            const float4* crow = reinterpret_cast<const float4*>(tb + r_b * SP);
            u64 a0 = 0ull, b0 = 0ull, a1 = 0ull, b1 = 0ull;
            #pragma unroll 8
            for (int k = 0; k < 32; k++) {
                float4 c  = crow[k];
                float4 qa = q0[k];
                float4 qb = q1[k];
                u64 cA = pack2(c.x, c.y), cB = pack2(c.z, c.w);
                a0 = ffma2(cA, pack2(qa.x, qa.y), a0);
                b0 = ffma2(cB, pack2(qa.z, qa.w), b0);
                a1 = ffma2(cA, pack2(qb.x, qb.y), a1);
                b1 = ffma2(cB, pack2(qb.z, qb.w), b1);
            }
            float l0, h0, l1, h1;
            unpack2(a0, l0, h0); unpack2(b0, l1, h1);
            float dot0 = (l0 + h0) + (l1 + h1);
            unpack2(a1, l0, h0); unpack2(b1, l1, h1);
            float dot1 = (l0 + h0) + (l1 + h1);
            bool valid = (i * TILE + r_b) < cnt;
            float e0 = valid ? __expf(dot0) : 0.f;
            float e1 = valid ? __expf(dot1) : 0.f;
            *reinterpret_cast<float2*>(&s_e[r_b][2 * sub]) = make_float2(e0, e1);
        }
        __syncthreads();

        // phase C: warp w accumulates all heads over rows w*8..w*8+7
        #pragma unroll
        for (int ii = 0; ii < 8; ii++) {
            int r = w * 8 + ii;
            float4 c = *reinterpret_cast<const float4*>(tb + r * SP + lane * 4);
            u64 cA = pack2(c.x, c.y), cB = pack2(c.z, c.w);
            float4 ev0 = *reinterpret_cast<const float4*>(&s_e[r][0]);
            float4 ev1 = *reinterpret_cast<const float4*>(&s_e[r][4]);
            float eh[8] = {ev0.x, ev0.y, ev0.z, ev0.w, ev1.x, ev1.y, ev1.z, ev1.w};
            #pragma unroll
            for (int h = 0; h < 8; h++) {
                u64 e2 = pack2(eh[h], eh[h]);
                acc2[h][0] = ffma2(e2, cA, acc2[h][0]);
                acc2[h][1] = ffma2(e2, cB, acc2[h][1]);
            }
            if (lane < 8) den_l += s_e[r][lane];
        }
        __syncthreads();
        load_tile(i + 2, i & 1);
    }
    cp_wait0();
    __syncthreads();

    // cross-warp reduction: reuse dynbuf stage0 as [8][8][128]
    {
        float* s_red = dynbuf;
        #pragma unroll
        for (int h = 0; h < 8; h++) {
            float x0, x1, x2, x3;
            unpack2(acc2[h][0], x0, x1); unpack2(acc2[h][1], x2, x3);
            *reinterpret_cast<float4*>(&s_red[(w * 8 + h) * 128 + lane * 4]) =
                make_float4(x0, x1, x2, x3);
        }
        if (lane < 8) s_den[w][lane] = den_l;
        __syncthreads();
        for (int kk = t; kk < 1024; kk += 256) {
            int h = kk >> 7, d = kk & 127;
            float s = 0.f;
            #pragma unroll
            for (int ww = 0; ww < 8; ww++) s += s_red[(ww * 8 + h) * 128 + d];
            s_sunf[h][d] = s;
        }
        if (t < 8) {
            float s = 0.f;
            #pragma unroll
            for (int ww = 0; ww < 8; ww++) s += s_den[ww][t];
            s_denf[t] = s;
        }
        __syncthreads();
    }

    // ---------------- x128[hid] = (sum_d sunf[h][d]*Wv[d][hid]) / den[h] ----------------
    {
        int col = t & 127, half = t >> 7, h = col >> 4;
        int db = half * 64;
        float a0 = 0.f, a1 = 0.f;
        #pragma unroll 8
        for (int d = 0; d < 64; d += 2) {
            a0 = fmaf(s_sunf[h][db + d],     __ldg(&Wv[(db + d)     * 128 + col]), a0);
            a1 = fmaf(s_sunf[h][db + d + 1], __ldg(&Wv[(db + d + 1) * 128 + col]), a1);
        }
        s_x128[half][col] = a0 + a1;
    }
    __syncthreads();
    if (t < 128) s_x128[0][t] = (s_x128[0][t] + s_x128[1][t]) / s_denf[t >> 4];
    __syncthreads();

    // prefetch pass-2 tiles (reverse order: most recently L2-resident first)
    load_tile(ntiles - 1, 0);
    load_tile(ntiles - 2, 1);

    // ---------------- xfc = x128 @ Wfc ----------------
    {
        int col = t & 127, half = t >> 7;
        int hb = half * 64;
        float a0 = 0.f, a1 = 0.f;
        #pragma unroll 8
        for (int i = 0; i < 64; i += 2) {
            a0 = fmaf(s_x128[0][hb + i],     __ldg(&Wfc[(hb + i)     * 128 + col]), a0);
            a1 = fmaf(s_x128[0][hb + i + 1], __ldg(&Wfc[(hb + i + 1) * 128 + col]), a1);
        }
        s_xfc[half][col] = a0 + a1;
    }
    __syncthreads();
    if (t < 128) s_xfc[0][t] = s_xfc[0][t] + s_xfc[1][t];
    __syncthreads();

    // ---------------- y[d] = nrm * sum_hid Wk[d][hid] * xfc[hid] ----------------
    {
        const float nrm = 0.088388347648318447f;  // 1/sqrt(128)
        float4 xv = *reinterpret_cast<const float4*>(&s_xfc[0][lane * 4]);
        #pragma unroll 4
        for (int dd = 0; dd < 16; dd++) {
            int d = w * 16 + dd;
            float4 wv = __ldg(reinterpret_cast<const float4*>(&Wk[d * 128 + lane * 4]));
            float p = fmaf(wv.w, xv.w, fmaf(wv.z, xv.z, fmaf(wv.y, xv.y, wv.x * xv.x)));
            p += __shfl_xor_sync(0xffffffffu, p, 16);
            p += __shfl_xor_sync(0xffffffffu, p, 8);
            p += __shfl_xor_sync(0xffffffffu, p, 4);
            p += __shfl_xor_sync(0xffffffffu, p, 2);
            p += __shfl_xor_sync(0xffffffffu, p, 1);
            if (lane == 0) s_y[d] = p * nrm;
        }
    }
    __syncthreads();

    // ---------------- pass 2: tiles in reverse, shuffle-free ----------------
    float Tf = 1.f;
    if (Tp) {
        unsigned r = *reinterpret_cast<const unsigned*>(Tp);
        float asf = __uint_as_float(r);
        Tf = (asf > 0.0078125f && asf < 1024.f) ? asf : (float)(int)r;
        if (!(Tf > 0.f)) Tf = 1.f;
    }
    const float invT = 1.0f / Tf;
    float den2_l = 0.f;

    for (int i = 0; i < ntiles; i++) {
        cp_wait1();
        __syncthreads();
        const int tile = ntiles - 1 - i;
        const float* tb = dynbuf + (i & 1) * TILE_FLOATS;
        {
            const float4* crow = reinterpret_cast<const float4*>(tb + r_b * SP);
            const float4* yrow = reinterpret_cast<const float4*>(s_y);
            u64 A = 0ull, B = 0ull;
            #pragma unroll 8
            for (int k = 0; k < 32; k++) {
                float4 c  = crow[k];
                float4 yv = yrow[k];
                A = ffma2(pack2(c.x, c.y), pack2(yv.x, yv.y), A);
                B = ffma2(pack2(c.z, c.w), pack2(yv.z, yv.w), B);
            }
            float lo, hi, lo2, hi2;
            unpack2(A, lo, hi); unpack2(B, lo2, hi2);
            float p  = (lo + hi) + (lo2 + hi2);
            float tt = __expf(2.f * p);
            float th = 1.f - __fdividef(2.f, tt + 1.f);   // tanh, inf-safe
            float pr = __expf(5.f * th * invT);
            int j = tile * TILE + r_b;
            if (sub == 0 && j < cnt) {
                s_p[(int)s_idx[j]] = pr;
                den2_l += pr;
            }
        }
        __syncthreads();
        load_tile(ntiles - 1 - (i + 2), i & 1);
    }
    cp_wait0();

    // reduce den2
    {
        float s = den2_l;
        s += __shfl_xor_sync(0xffffffffu, s, 16);
        s += __shfl_xor_sync(0xffffffffu, s, 8);
        s += __shfl_xor_sync(0xffffffffu, s, 4);
        s += __shfl_xor_sync(0xffffffffu, s, 2);
        s += __shfl_xor_sync(0xffffffffu, s, 1);
        if (lane == 0) s_den2[w] = s;
    }
    __syncthreads();
    if (t == 0) {
        float s = 0.f;
        #pragma unroll
        for (int ww = 0; ww < 8; ww++) s += s_den2[ww];
        s_inv = 1.0f / s;
    }
    __syncthreads();

    const float inv = s_inv;
    float* outb = out + (size_t)b * NN;
    for (int i = t; i < NN; i += 256) outb[i] = s_p[i] * inv;
}

extern "C" void kernel_launch(void* const* d_in, const int* in_sizes, int n_in,
                              void* d_out, int out_size) {
    (void)in_sizes; (void)out_size;
    const float* state = (const float*)d_in[0];
    const float* ctx   = (const float*)d_in[1];
    const int*   mask  = (const int*)d_in[2];
    const float* Wq    = (const float*)d_in[3];
    const float* Wkm   = (const float*)d_in[4];
    const float* Wv    = (const float*)d_in[5];
    const float* Wfc   = (const float*)d_in[6];
    const float* Wk    = (const float*)d_in[7];
    const int*   Tp    = (n_in > 8) ? (const int*)d_in[8] : nullptr;

    cudaFuncSetAttribute(fused_ptr_attn_kernel,
                         cudaFuncAttributeMaxDynamicSharedMemorySize, 2 * TILE_BYTES);
    fused_ptr_attn_kernel<<<NB, 256, 2 * TILE_BYTES>>>(state, ctx, mask, Wq, Wkm, Wv,
                                                       Wfc, Wk, Tp, (float*)d_out);
}

// round 7
// speedup vs baseline: 1.0015x; 1.0015x over previous
#include <cuda_runtime.h>
#include <cstdint>
#include <cstddef>

#define NB 512
#define NN 1000
#define TILE 64
#define SP 132                       // padded floats per tile row (128+4)
#define TILE_FLOATS (TILE * SP)      // 8448
#define TILE_BYTES (TILE_FLOATS * 4) // 33792

using u64 = unsigned long long;

__device__ __forceinline__ u64 pack2(float lo, float hi) {
    u64 r; asm("mov.b64 %0, {%1, %2};" : "=l"(r) : "f"(lo), "f"(hi)); return r;
}
__device__ __forceinline__ void unpack2(u64 v, float& lo, float& hi) {
    asm("mov.b64 {%0, %1}, %2;" : "=f"(lo), "=f"(hi) : "l"(v));
}
__device__ __forceinline__ u64 ffma2(u64 a, u64 b, u64 c) {
    u64 d; asm("fma.rn.f32x2 %0, %1, %2, %3;" : "=l"(d) : "l"(a), "l"(b), "l"(c)); return d;
}
__device__ __forceinline__ void cp16(uint32_t s, const void* g) {
    asm volatile("cp.async.cg.shared.global [%0], [%1], 16;" :: "r"(s), "l"(g));
}
__device__ __forceinline__ void cp_commit() { asm volatile("cp.async.commit_group;"); }
__device__ __forceinline__ void cp_wait1() { asm volatile("cp.async.wait_group 1;"); }
__device__ __forceinline__ void cp_wait0() { asm volatile("cp.async.wait_group 0;"); }

__global__ __launch_bounds__(256, 2)
void fused_ptr_attn_kernel(const float* __restrict__ state,   // [B,384]
                           const float* __restrict__ ctx,     // [B,N,128]
                           const int*   __restrict__ mask,    // [B,N]
                           const float* __restrict__ Wq,      // [384,128]
                           const float* __restrict__ Wkm,     // [128,128]
                           const float* __restrict__ Wv,      // [128,128]
                           const float* __restrict__ Wfc,     // [128,128]
                           const float* __restrict__ Wk,      // [128,128]
                           const int*   __restrict__ Tp,
                           float* __restrict__ out)           // [B,N]
{
    extern __shared__ __align__(16) float dynbuf[];  // 2 * TILE_FLOATS

    __shared__ __align__(16) float s_state[384];
    __shared__ __align__(16) float s_q[128];
    __shared__ __align__(16) float s_Qt[8][SP];    // padded rows: conflict-free head reads
    __shared__ __align__(16) float s_e[TILE][8];
    __shared__ __align__(16) float s_sunf[8][128];
    __shared__ __align__(16) float s_x128[2][128];
    __shared__ __align__(16) float s_xfc[2][128];
    __shared__ __align__(16) float s_y[128];
    __shared__ __align__(16) float s_p[NN];
    __shared__ short s_idx[NN];
    __shared__ int   s_cnt;
    __shared__ float s_den[8][8];
    __shared__ float s_denf[8];
    __shared__ float s_den2[8];
    __shared__ float s_inv;

    const int t    = threadIdx.x;
    const int w    = t >> 5;
    const int lane = t & 31;
    const int b    = blockIdx.x;
    const float4* ctx4 = reinterpret_cast<const float4*>(ctx + (size_t)b * NN * 128);
    const uint32_t dyn_s = (uint32_t)__cvta_generic_to_shared(dynbuf);

    // ---------------- prologue ----------------
    if (t < 128) {
        s_state[t]       = state[(size_t)b * 384 + t];
        s_state[t + 128] = state[(size_t)b * 384 + 128 + t];
        s_state[t + 256] = state[(size_t)b * 384 + 256 + t];
    }
    for (int i = t; i < NN; i += 256) s_p[i] = 0.f;
    __syncthreads();

    // warp 0: compact unmasked indices; threads 128..255: q = state @ Wq
    if (w == 0) {
        int base = 0;
        const int* mb = mask + (size_t)b * NN;
        for (int i0 = 0; i0 < NN; i0 += 32) {
            int n = i0 + lane;
            int m = (n < NN) ? __ldg(&mb[n]) : 1;
            unsigned bal = __ballot_sync(0xffffffffu, m == 0);
            if (m == 0) {
                int pre = __popc(bal & ((1u << lane) - 1u));
                s_idx[base + pre] = (short)n;
            }
            base += __popc(bal);
        }
        if (lane == 0) s_cnt = base;
    } else if (t >= 128) {
        int col = t - 128;
        float a0 = 0.f, a1 = 0.f, a2 = 0.f, a3 = 0.f;
        #pragma unroll 4
        for (int i = 0; i < 384; i += 4) {
            a0 = fmaf(s_state[i    ], __ldg(&Wq[(i    ) * 128 + col]), a0);
            a1 = fmaf(s_state[i + 1], __ldg(&Wq[(i + 1) * 128 + col]), a1);
            a2 = fmaf(s_state[i + 2], __ldg(&Wq[(i + 2) * 128 + col]), a2);
            a3 = fmaf(s_state[i + 3], __ldg(&Wq[(i + 3) * 128 + col]), a3);
        }
        s_q[col] = (a0 + a1) + (a2 + a3);
    }
    __syncthreads();

    const int cnt    = s_cnt;
    const int ntiles = (cnt + TILE - 1) / TILE;

    // tile loader: one warp per 8 rows, one row per warp-iteration (coalesced 512B)
    auto load_tile = [&](int tile, int stage) {
        if ((unsigned)tile < (unsigned)ntiles) {
            uint32_t base = dyn_s + stage * TILE_BYTES;
            #pragma unroll
            for (int i = 0; i < 8; i++) {
                int j = tile * TILE + w * 8 + i;
                int n = (j < cnt) ? (int)s_idx[j] : (int)s_idx[0];
                cp16(base + ((w * 8 + i) * SP + lane * 4) * 4, ctx4 + n * 32 + lane);
            }
        }
        cp_commit();
    };

    // kick off tiles 0,1 before Qt compute (covers initial DRAM latency)
    load_tile(0, 0);
    load_tile(1, 1);

    // ---------------- Qt[h][d] = 0.25 * sum_j Wkm[d][16h+j] * q[16h+j] ----------------
    {
        const int hw    = w & 3;
        const int dbase = (w >> 2) * 64;
        const int hid   = hw * 32 + lane;
        const float ql  = s_q[hid];
        const int head0 = hw * 2 + (lane >> 4);
        #pragma unroll 4
        for (int dd = 0; dd < 64; dd++) {
            int d = dbase + dd;
            float p = __ldg(&Wkm[d * 128 + hid]) * ql;
            p += __shfl_xor_sync(0xffffffffu, p, 8);
            p += __shfl_xor_sync(0xffffffffu, p, 4);
            p += __shfl_xor_sync(0xffffffffu, p, 2);
            p += __shfl_xor_sync(0xffffffffu, p, 1);
            if ((lane & 15) == 0) s_Qt[head0][d] = 0.25f * p;
        }
    }
    __syncthreads();

    // ---------------- pass 1: tiles, shuffle-free ----------------
    u64 acc2[8][2];
    #pragma unroll
    for (int h = 0; h < 8; h++) { acc2[h][0] = 0ull; acc2[h][1] = 0ull; }
    float den_l = 0.f;

    const int r_b   = t >> 2;        // phase-B row
    const int sub   = t & 3;         // phase-B head pair
    const float4* q0 = reinterpret_cast<const float4*>(s_Qt[2 * sub]);
    const float4* q1 = reinterpret_cast<const float4*>(s_Qt[2 * sub + 1]);

    for (int i = 0; i < ntiles; i++) {
        cp_wait1();
        __syncthreads();
        const float* tb = dynbuf + (i & 1) * TILE_FLOATS;

        // phase B: dots + exp, one thread per (row, head-pair)
        {
            const float4* crow = reinterpret_cast<const float4*>(tb + r_b * SP);
            u64 a0 = 0ull, b0 = 0ull, a1 = 0ull, b1 = 0ull;
            #pragma unroll 8
            for (int k = 0; k < 32; k++) {
                float4 c  = crow[k];
                float4 qa = q0[k];
                float4 qb = q1[k];
                u64 cA = pack2(c.x, c.y), cB = pack2(c.z, c.w);
                a0 = ffma2(cA, pack2(qa.x, qa.y), a0);
                b0 = ffma2(cB, pack2(qa.z, qa.w), b0);
                a1 = ffma2(cA, pack2(qb.x, qb.y), a1);
                b1 = ffma2(cB, pack2(qb.z, qb.w), b1);
            }
            float l0, h0, l1, h1;
            unpack2(a0, l0, h0); unpack2(b0, l1, h1);
            float dot0 = (l0 + h0) + (l1 + h1);
            unpack2(a1, l0, h0); unpack2(b1, l1, h1);
            float dot1 = (l0 + h0) + (l1 + h1);
            bool valid = (i * TILE + r_b) < cnt;
            float e0 = valid ? __expf(dot0) : 0.f;
            float e1 = valid ? __expf(dot1) : 0.f;
            *reinterpret_cast<float2*>(&s_e[r_b][2 * sub]) = make_float2(e0, e1);
        }
        __syncthreads();

        // phase C: warp w accumulates all heads over rows w*8..w*8+7
        #pragma unroll
        for (int ii = 0; ii < 8; ii++) {
            int r = w * 8 + ii;
            float4 c = *reinterpret_cast<const float4*>(tb + r * SP + lane * 4);
            u64 cA = pack2(c.x, c.y), cB = pack2(c.z, c.w);
            float4 ev0 = *reinterpret_cast<const float4*>(&s_e[r][0]);
            float4 ev1 = *reinterpret_cast<const float4*>(&s_e[r][4]);
            float eh[8] = {ev0.x, ev0.y, ev0.z, ev0.w, ev1.x, ev1.y, ev1.z, ev1.w};
            #pragma unroll
            for (int h = 0; h < 8; h++) {
                u64 e2 = pack2(eh[h], eh[h]);
                acc2[h][0] = ffma2(e2, cA, acc2[h][0]);
                acc2[h][1] = ffma2(e2, cB, acc2[h][1]);
            }
            if (lane < 8) den_l += s_e[r][lane];
        }
        __syncthreads();
        load_tile(i + 2, i & 1);
    }
    cp_wait0();
    __syncthreads();

    // cross-warp reduction: reuse dynbuf stage0 as [8][8][128]
    {
        float* s_red = dynbuf;
        #pragma unroll
        for (int h = 0; h < 8; h++) {
            float x0, x1, x2, x3;
            unpack2(acc2[h][0], x0, x1); unpack2(acc2[h][1], x2, x3);
            *reinterpret_cast<float4*>(&s_red[(w * 8 + h) * 128 + lane * 4]) =
                make_float4(x0, x1, x2, x3);
        }
        if (lane < 8) s_den[w][lane] = den_l;
        __syncthreads();
        for (int kk = t; kk < 1024; kk += 256) {
            int h = kk >> 7, d = kk & 127;
            float s = 0.f;
            #pragma unroll
            for (int ww = 0; ww < 8; ww++) s += s_red[(ww * 8 + h) * 128 + d];
            s_sunf[h][d] = s;
        }
        if (t < 8) {
            float s = 0.f;
            #pragma unroll
            for (int ww = 0; ww < 8; ww++) s += s_den[ww][t];
            s_denf[t] = s;
        }
        __syncthreads();
    }

    // ---------------- x128[hid] = (sum_d sunf[h][d]*Wv[d][hid]) / den[h] ----------------
    {
        int col = t & 127, half = t >> 7, h = col >> 4;
        int db = half * 64;
        float a0 = 0.f, a1 = 0.f;
        #pragma unroll 8
        for (int d = 0; d < 64; d += 2) {
            a0 = fmaf(s_sunf[h][db + d],     __ldg(&Wv[(db + d)     * 128 + col]), a0);
            a1 = fmaf(s_sunf[h][db + d + 1], __ldg(&Wv[(db + d + 1) * 128 + col]), a1);
        }
        s_x128[half][col] = a0 + a1;
    }
    __syncthreads();
    if (t < 128) s_x128[0][t] = (s_x128[0][t] + s_x128[1][t]) / s_denf[t >> 4];
    __syncthreads();

    // prefetch pass-2 tiles (reverse order: most recently L2-resident first)
    load_tile(ntiles - 1, 0);
    load_tile(ntiles - 2, 1);

    // ---------------- xfc = x128 @ Wfc ----------------
    {
        int col = t & 127, half = t >> 7;
        int hb = half * 64;
        float a0 = 0.f, a1 = 0.f;
        #pragma unroll 8
        for (int i = 0; i < 64; i += 2) {
            a0 = fmaf(s_x128[0][hb + i],     __ldg(&Wfc[(hb + i)     * 128 + col]), a0);
            a1 = fmaf(s_x128[0][hb + i + 1], __ldg(&Wfc[(hb + i + 1) * 128 + col]), a1);
        }
        s_xfc[half][col] = a0 + a1;
    }
    __syncthreads();
    if (t < 128) s_xfc[0][t] = s_xfc[0][t] + s_xfc[1][t];
    __syncthreads();

    // ---------------- y[d] = nrm * sum_hid Wk[d][hid] * xfc[hid] ----------------
    {
        const float nrm = 0.088388347648318447f;  // 1/sqrt(128)
        float4 xv = *reinterpret_cast<const float4*>(&s_xfc[0][lane * 4]);
        #pragma unroll 4
        for (int dd = 0; dd < 16; dd++) {
            int d = w * 16 + dd;
            float4 wv = __ldg(reinterpret_cast<const float4*>(&Wk[d * 128 + lane * 4]));
            float p = fmaf(wv.w, xv.w, fmaf(wv.z, xv.z, fmaf(wv.y, xv.y, wv.x * xv.x)));
            p += __shfl_xor_sync(0xffffffffu, p, 16);
            p += __shfl_xor_sync(0xffffffffu, p, 8);
            p += __shfl_xor_sync(0xffffffffu, p, 4);
            p += __shfl_xor_sync(0xffffffffu, p, 2);
            p += __shfl_xor_sync(0xffffffffu, p, 1);
            if (lane == 0) s_y[d] = p * nrm;
        }
    }
    __syncthreads();

    // ---------------- pass 2: tiles in reverse, shuffle-free ----------------
    float Tf = 1.f;
    if (Tp) {
        unsigned r = *reinterpret_cast<const unsigned*>(Tp);
        float asf = __uint_as_float(r);
        Tf = (asf > 0.0078125f && asf < 1024.f) ? asf : (float)(int)r;
        if (!(Tf > 0.f)) Tf = 1.f;
    }
    const float invT = 1.0f / Tf;
    float den2_l = 0.f;

    for (int i = 0; i < ntiles; i++) {
        cp_wait1();
        __syncthreads();
        const int tile = ntiles - 1 - i;
        const float* tb = dynbuf + (i & 1) * TILE_FLOATS;
        {
            const float4* crow = reinterpret_cast<const float4*>(tb + r_b * SP);
            const float4* yrow = reinterpret_cast<const float4*>(s_y);
            u64 A = 0ull, B = 0ull;
            #pragma unroll 8
            for (int k = 0; k < 32; k++) {
                float4 c  = crow[k];
                float4 yv = yrow[k];
                A = ffma2(pack2(c.x, c.y), pack2(yv.x, yv.y), A);
                B = ffma2(pack2(c.z, c.w), pack2(yv.z, yv.w), B);
            }
            float lo, hi, lo2, hi2;
            unpack2(A, lo, hi); unpack2(B, lo2, hi2);
            float p  = (lo + hi) + (lo2 + hi2);
            float tt = __expf(2.f * p);
            float th = 1.f - __fdividef(2.f, tt + 1.f);   // tanh, inf-safe
            float pr = __expf(5.f * th * invT);
            int j = tile * TILE + r_b;
            if (sub == 0 && j < cnt) {
                s_p[(int)s_idx[j]] = pr;
                den2_l += pr;
            }
        }
        __syncthreads();
        load_tile(ntiles - 1 - (i + 2), i & 1);
    }
    cp_wait0();

    // reduce den2
    {
        float s = den2_l;
        s += __shfl_xor_sync(0xffffffffu, s, 16);
        s += __shfl_xor_sync(0xffffffffu, s, 8);
        s += __shfl_xor_sync(0xffffffffu, s, 4);
        s += __shfl_xor_sync(0xffffffffu, s, 2);
        s += __shfl_xor_sync(0xffffffffu, s, 1);
        if (lane == 0) s_den2[w] = s;
    }
    __syncthreads();
    if (t == 0) {
        float s = 0.f;
        #pragma unroll
        for (int ww = 0; ww < 8; ww++) s += s_den2[ww];
        s_inv = 1.0f / s;
    }
    __syncthreads();

    const float inv = s_inv;
    float* outb = out + (size_t)b * NN;
    for (int i = t; i < NN; i += 256) outb[i] = s_p[i] * inv;
}

extern "C" void kernel_launch(void* const* d_in, const int* in_sizes, int n_in,
                              void* d_out, int out_size) {
    (void)in_sizes; (void)out_size;
    const float* state = (const float*)d_in[0];
    const float* ctx   = (const float*)d_in[1];
    const int*   mask  = (const int*)d_in[2];
    const float* Wq    = (const float*)d_in[3];
    const float* Wkm   = (const float*)d_in[4];
    const float* Wv    = (const float*)d_in[5];
    const float* Wfc   = (const float*)d_in[6];
    const float* Wk    = (const float*)d_in[7];
    const int*   Tp    = (n_in > 8) ? (const int*)d_in[8] : nullptr;

    cudaFuncSetAttribute(fused_ptr_attn_kernel,
                         cudaFuncAttributeMaxDynamicSharedMemorySize, 2 * TILE_BYTES);
    fused_ptr_attn_kernel<<<NB, 256, 2 * TILE_BYTES>>>(state, ctx, mask, Wq, Wkm, Wv,
                                                       Wfc, Wk, Tp, (float*)d_out);
}